// round 14
// baseline (speedup 1.0000x reference)
#include <cuda_runtime.h>
#include <cuda_fp16.h>
#include <math.h>
#include <stdint.h>

#define NN 512
#define CZ 128
#define NROW (NN*NN)          // 262144 rows

// ---------------- scratch (static device globals) ---------------------------
__device__ __half g_LThi[(size_t)CZ*NROW];  // [c][i*512+k] fp16
__device__ __half g_RThi[(size_t)CZ*NROW];  // [c][j*512+k] fp16
__device__ __half g_glsig[(size_t)NROW*CZ]; // fp16, row-major (r, c)
__device__ __half g_einH [(size_t)CZ*NROW]; // [c][i*512+j] fp16
// weights fp16 (hi only), [n][k]: rows 0-255 gate, 256-511 proj, 512-639 gl, 640-767 outp
__device__ __half g_Whi[768*128];

// ======================= PTX helpers (sm_103-safe) ==========================
__device__ __forceinline__ uint32_t smem_u32(const void* p) {
    uint32_t a;
    asm("{ .reg .u64 t; cvta.to.shared.u64 t, %1; cvt.u32.u64 %0, t; }" : "=r"(a) : "l"(p));
    return a;
}
__device__ __forceinline__ void ldsm4(uint32_t r[4], uint32_t addr) {
    asm volatile("ldmatrix.sync.aligned.m8n8.x4.shared.b16 {%0,%1,%2,%3}, [%4];"
        : "=r"(r[0]), "=r"(r[1]), "=r"(r[2]), "=r"(r[3]) : "r"(addr));
}
__device__ __forceinline__ void mma16816(float c[4], const uint32_t a[4],
                                         uint32_t b0, uint32_t b1) {
    asm volatile("mma.sync.aligned.m16n8k16.row.col.f32.f16.f16.f32 "
        "{%0,%1,%2,%3}, {%4,%5,%6,%7}, {%8,%9}, {%0,%1,%2,%3};"
        : "+f"(c[0]), "+f"(c[1]), "+f"(c[2]), "+f"(c[3])
        : "r"(a[0]), "r"(a[1]), "r"(a[2]), "r"(a[3]), "r"(b0), "r"(b1));
}
__device__ __forceinline__ void cp16(uint32_t dst, const void* src) {
    asm volatile("cp.async.cg.shared.global [%0], [%1], 16;" :: "r"(dst), "l"(src));
}
#define CP_COMMIT() asm volatile("cp.async.commit_group;" ::: "memory")
// fast sigmoid: MUFU.EX2 path + fast division; rel err ~1e-6 << budget
__device__ __forceinline__ float sigf(float x) {
    return __fdividef(1.f, 1.f + __expf(-x));
}

// ---------------- K0: weights -> fp16 ---------------------------------------
__global__ void wsplit(const float* __restrict__ pw, const float* __restrict__ gw,
                       const float* __restrict__ glw, const float* __restrict__ ow)
{
    int idx = blockIdx.x*256 + threadIdx.x;   // 384*256 = 98304 = 768*128
    int row = idx >> 7;
    float v;
    if      (row < 256) v = gw [idx];
    else if (row < 512) v = pw [idx - 256*128];
    else if (row < 640) v = glw[idx - 512*128];
    else                v = ow [idx - 640*128];
    g_Whi[idx] = __float2half_rn(v);
}

// =================== mma-based LN+GEMM machinery (k1/k3) ====================
#define ARS    272                 // A row stride  (128 fp16 = 256B + pad)
#define BRS    272
#define AHI    0                   // A: 128*272 = 34816
#define BHI    34816               // B hi: 128 rows -> 34816 (k1 staging OVERLAYS here)
#define SCS    272                 // k1 staging col stride ([col][row], 64 cols)
#define SMEM13 69632               // k1: A + B(=staging); 3 blocks/SM
// k3f (R12 128-row version): A + tileH(=BHI region, weights after) + partials
#define TFSH   136                 // half stride of einH tile (272 B rows)
#define PSUM   69632               // 4 x 128 floats = 2048 B
#define PSQ    71680
#define SMEM_K3 73728              // 3 blocks/SM

// LN 128 rows of src -> fp16 A tile in smem (row-major [row][k])
__device__ __forceinline__ void ln_quant(const float* __restrict__ src,
                                         const float* __restrict__ w,
                                         const float* __restrict__ b,
                                         int r0, int tid, char* sb)
{
    int wid = tid >> 5, lane = tid & 31;
    float4 wv = *(const float4*)(w + lane*4);
    float4 bv = *(const float4*)(b + lane*4);
#pragma unroll
    for (int q = 0; q < 16; q++) {
        int row = wid*16 + q;
        float4 x = *(const float4*)(src + (size_t)(r0+row)*CZ + lane*4);
        float s  = x.x+x.y+x.z+x.w;
        float sq = x.x*x.x + x.y*x.y + x.z*x.z + x.w*x.w;
#pragma unroll
        for (int o = 16; o > 0; o >>= 1) {
            s  += __shfl_xor_sync(0xffffffffu, s,  o);
            sq += __shfl_xor_sync(0xffffffffu, sq, o);
        }
        float m  = s * (1.f/CZ);
        float v  = sq * (1.f/CZ) - m*m;
        float rs = rsqrtf(v + 1e-5f);
        float y0 = (x.x-m)*rs*wv.x + bv.x;
        float y1 = (x.y-m)*rs*wv.y + bv.y;
        float y2 = (x.z-m)*rs*wv.z + bv.z;
        float y3 = (x.w-m)*rs*wv.w + bv.w;
        uint32_t off = (uint32_t)(row*ARS + lane*8);
        *(__half2*)(sb + AHI + off)     = __floats2half2_rn(y0, y1);
        *(__half2*)(sb + AHI + off + 4) = __floats2half2_rn(y2, y3);
    }
}

// gate rows 0-63 | proj rows 64-127 -> BHI (k1)
__device__ __forceinline__ void load_w_gp(int nt, int tid, char* sb)
{
#pragma unroll
    for (int q = 0; q < 8; q++) {
        int idx = tid + q*256;
        int row = idx >> 4, ch = idx & 15;
        int gr = (row < 64) ? (nt*64 + row) : (256 + nt*64 + row - 64);
        *(uint4*)(sb + BHI + row*BRS + ch*16) = *(const uint4*)(g_Whi + (size_t)gr*128 + ch*8);
    }
}

// 128 contiguous weight rows (base row0) -> smem at byte offset dstOff
__device__ __forceinline__ void load_w_128(int row0, int tid, char* sb, int dstOff)
{
#pragma unroll
    for (int q = 0; q < 8; q++) {
        int idx = tid + q*256;
        int row = idx >> 4, ch = idx & 15;
        *(uint4*)(sb + dstOff + row*BRS + ch*16) = *(const uint4*)(g_Whi + (size_t)(row0 + row)*128 + ch*8);
    }
}

// generic single-pass warp-tile mma: A base aB, B base bB (absolute smem addrs)
__device__ __forceinline__ void mma_tile1(uint32_t aB, uint32_t bB,
                                          const uint32_t aOff[2],
                                          const uint32_t bOff[2], float acc[2][4][4])
{
#pragma unroll
    for (int fm = 0; fm < 2; fm++)
#pragma unroll
        for (int fn = 0; fn < 4; fn++)
#pragma unroll
            for (int e = 0; e < 4; e++) acc[fm][fn][e] = 0.f;
#pragma unroll
    for (int kk = 0; kk < 8; kk++) {
        uint32_t ah[2][4], bh[2][4];
#pragma unroll
        for (int fm = 0; fm < 2; fm++)
            ldsm4(ah[fm], aB + aOff[fm] + kk*32);
#pragma unroll
        for (int fp = 0; fp < 2; fp++)
            ldsm4(bh[fp], bB + bOff[fp] + kk*32);
#pragma unroll
        for (int fm = 0; fm < 2; fm++)
#pragma unroll
            for (int fn = 0; fn < 4; fn++) {
                int fp = fn >> 1, s = (fn & 1)*2;
                mma16816(acc[fm][fn], ah[fm], bh[fp][s], bh[fp][s+1]);
            }
    }
}

// ---------------- K1: LN + gate/proj/gl, 3 blocks/SM ------------------------
__global__ __launch_bounds__(256, 3) void k1(const float* __restrict__ act,
                                             const float* __restrict__ mask,
                                             const float* __restrict__ lnw,
                                             const float* __restrict__ lnb,
                                             const float* __restrict__ pb,
                                             const float* __restrict__ gb,
                                             const float* __restrict__ glb)
{
    extern __shared__ char sb[];
    uint32_t sbase = smem_u32(sb);
    int tid = threadIdx.x, wid = tid >> 5, lane = tid & 31;
    int r0 = blockIdx.x * 128;
    int wm = wid & 3, wn = wid >> 2;
    int RM = wm*32, RNl = wn*32;
    int rr = lane >> 2, cp = (lane & 3)*2;

    uint32_t aOff[2], bOff[2], bOffP[2];
#pragma unroll
    for (int fm = 0; fm < 2; fm++)
        aOff[fm] = (uint32_t)((RM + fm*16 + (lane & 15))*ARS + (lane >> 4)*16);
#pragma unroll
    for (int fp = 0; fp < 2; fp++) {
        bOff[fp]  = (uint32_t)((RNl + fp*16 + ((lane >> 4) << 3) + (lane & 7))*BRS
                               + ((lane >> 3) & 1)*16);
        bOffP[fp] = bOff[fp] + 64*BRS;
    }

    ln_quant(act, lnw, lnb, r0, tid, sb);

    float acc[2][4][4];
    __half2 sigA[2][4], sigB[2][4];     // packed gate sigmoids (16 regs)

    // ---- 4 tiles of 64 cols: gate then proj (acc reused); staging = B region
    for (int nt = 0; nt < 4; nt++) {
        load_w_gp(nt, tid, sb);                    // gate hi | proj hi
        __syncthreads();                           // B (and A on nt=0) visible
        mma_tile1(sbase + AHI, sbase + BHI, aOff, bOff, acc);   // gate
#pragma unroll
        for (int fm = 0; fm < 2; fm++)
#pragma unroll
            for (int fn = 0; fn < 4; fn++) {
                int c0 = nt*64 + RNl + fn*8 + cp;
                float2 gbv = *(const float2*)(gb + c0);
                sigA[fm][fn] = __floats2half2_rn(sigf(acc[fm][fn][0] + gbv.x),
                                                 sigf(acc[fm][fn][1] + gbv.y));
                sigB[fm][fn] = __floats2half2_rn(sigf(acc[fm][fn][2] + gbv.x),
                                                 sigf(acc[fm][fn][3] + gbv.y));
            }
        mma_tile1(sbase + AHI, sbase + BHI, aOff, bOffP, acc);  // proj
        __syncthreads();                           // all warps done reading B
#pragma unroll
        for (int fm = 0; fm < 2; fm++) {
            int rowA = RM + fm*16 + rr;
            float mkA = mask[r0 + rowA];
            float mkB = mask[r0 + rowA + 8];
#pragma unroll
            for (int fn = 0; fn < 4; fn++) {
                int cl = RNl + fn*8 + cp;
                float2 pbv = *(const float2*)(pb + nt*64 + cl);
                float2 sA = __half22float2(sigA[fm][fn]);
                float2 sB = __half22float2(sigB[fm][fn]);
                float vA0 = mkA*(acc[fm][fn][0] + pbv.x)*sA.x;
                float vA1 = mkA*(acc[fm][fn][1] + pbv.y)*sA.y;
                float vB0 = mkB*(acc[fm][fn][2] + pbv.x)*sB.x;
                float vB1 = mkB*(acc[fm][fn][3] + pbv.y)*sB.y;
                uint32_t o = (uint32_t)(BHI + cl*SCS + rowA*2);
                *(__half*)(sb + o)             = __float2half_rn(vA0);
                *(__half*)(sb + o + SCS)       = __float2half_rn(vA1);
                *(__half*)(sb + o + 16)        = __float2half_rn(vB0);
                *(__half*)(sb + o + SCS + 16)  = __float2half_rn(vB1);
            }
        }
        __syncthreads();                           // staging visible
        {
            __half* dst = (nt < 2) ? g_LThi : g_RThi;
            int cl = tid >> 2, rs = (tid & 3)*32;
            size_t go = (size_t)((nt & 1)*64 + cl)*NROW + r0 + rs;
            uint32_t so = (uint32_t)(BHI + cl*SCS + rs*2);
#pragma unroll
            for (int s = 0; s < 4; s++)
                *(uint4*)(dst + go + s*8) = *(const uint4*)(sb + so + s*16);
        }
        __syncthreads();                           // staging reads done before B reload
    }

    // ---- gl gate: two single passes ----
    load_w_128(512, tid, sb, BHI);
    __syncthreads();
    for (int nt = 0; nt < 2; nt++) {
        mma_tile1(sbase + AHI, sbase + BHI, aOff, nt ? bOffP : bOff, acc);
#pragma unroll
        for (int fm = 0; fm < 2; fm++) {
            int rowA = RM + fm*16 + rr;
#pragma unroll
            for (int fn = 0; fn < 4; fn++) {
                int c0 = nt*64 + RNl + fn*8 + cp;
                float2 bv = *(const float2*)(glb + c0);
                *(__half2*)(g_glsig + (size_t)(r0 + rowA)*CZ + c0) =
                    __floats2half2_rn(sigf(acc[fm][fn][0] + bv.x), sigf(acc[fm][fn][1] + bv.y));
                *(__half2*)(g_glsig + (size_t)(r0 + rowA + 8)*CZ + c0) =
                    __floats2half2_rn(sigf(acc[fm][fn][2] + bv.x), sigf(acc[fm][fn][3] + bv.y));
            }
        }
    }
}

// ---------------- K2: fp16 single-pass GEMM, K-chunk 64, 3-stage (FROZEN) ---
#define RSTRIDE 144
#define KCOMP   (128*RSTRIDE)       // 18432
#define ST_A    0
#define ST_BH   KCOMP
#define STAGE   (2*KCOMP)           // 36864
#define SMEM_K2 (3*STAGE)           // 110592 -> 2 blocks/SM

__device__ __forceinline__ void k2_compute(uint32_t sbk, const uint32_t aOff[2],
                                           const uint32_t bOff[4], float acc[2][8][4])
{
#pragma unroll
    for (int kk = 0; kk < 4; kk++) {
        uint32_t ah[2][4], bh[4][4];
#pragma unroll
        for (int fm = 0; fm < 2; fm++)
            ldsm4(ah[fm], sbk + ST_A + aOff[fm] + kk*32);
#pragma unroll
        for (int fp = 0; fp < 4; fp++)
            ldsm4(bh[fp], sbk + ST_BH + bOff[fp] + kk*32);
#pragma unroll
        for (int fm = 0; fm < 2; fm++)
#pragma unroll
            for (int fn = 0; fn < 8; fn++) {
                int fp = fn >> 1, s = (fn & 1)*2;
                mma16816(acc[fm][fn], ah[fm], bh[fp][s], bh[fp][s+1]);
            }
    }
}

__device__ __forceinline__ void k2_copy(uint32_t st, const __half* Ah,
                                        const __half* Bh, int k0, int tid)
{
#pragma unroll
    for (int q = 0; q < 4; q++) {
        int idx = tid + q*256;          // 0..1023
        int r = idx >> 3, kg = idx & 7;
        size_t go = (size_t)r*NN + k0 + kg*8;
        uint32_t so = (uint32_t)(r*RSTRIDE + kg*16);
        cp16(st + ST_A  + so, Ah + go);
        cp16(st + ST_BH + so, Bh + go);
    }
}

__global__ __launch_bounds__(256, 2) void k2()
{
    extern __shared__ char sb[];
    uint32_t sbase = smem_u32(sb);
    int tid = threadIdx.x, wid = tid >> 5, lane = tid & 31;
    int c  = blockIdx.y;
    int ti = blockIdx.x >> 2, tj = blockIdx.x & 3;

    const __half* Ah = g_LThi + (size_t)c*NROW + (size_t)ti*128*NN;
    const __half* Bh = g_RThi + (size_t)c*NROW + (size_t)tj*128*NN;
    __half* C = g_einH + (size_t)c*NROW + (size_t)(ti*128)*NN + tj*128;

    int wm = wid & 3, wn = wid >> 2;
    int RM = wm*32, RN = wn*64;

    uint32_t aOff[2], bOff[4];
#pragma unroll
    for (int fm = 0; fm < 2; fm++)
        aOff[fm] = (uint32_t)((RM + fm*16 + (lane & 15))*RSTRIDE + (lane >> 4)*16);
#pragma unroll
    for (int fp = 0; fp < 4; fp++)
        bOff[fp] = (uint32_t)((RN + fp*16 + ((lane >> 4) << 3) + (lane & 7))*RSTRIDE
                              + ((lane >> 3) & 1)*16);

    float acc[2][8][4];
#pragma unroll
    for (int fm = 0; fm < 2; fm++)
#pragma unroll
        for (int fn = 0; fn < 8; fn++)
#pragma unroll
            for (int e = 0; e < 4; e++) acc[fm][fn][e] = 0.f;

    k2_copy(sbase + 0*STAGE, Ah, Bh, 0,  tid); CP_COMMIT();
    k2_copy(sbase + 1*STAGE, Ah, Bh, 64, tid); CP_COMMIT();

    for (int t = 0; t < 8; t++) {
        if (t < 7) asm volatile("cp.async.wait_group 1;" ::: "memory");
        else       asm volatile("cp.async.wait_group 0;" ::: "memory");
        __syncthreads();
        if (t + 2 < 8) {
            k2_copy(sbase + ((t+2)%3)*STAGE, Ah, Bh, (t+2)*64, tid);
            CP_COMMIT();
        }
        k2_compute(sbase + (t%3)*STAGE, aOff, bOff, acc);
    }

    int rr = lane >> 2, cp = (lane & 3)*2;
#pragma unroll
    for (int fm = 0; fm < 2; fm++)
#pragma unroll
        for (int fn = 0; fn < 8; fn++) {
            int row = RM + fm*16 + rr;
            int col = RN + fn*8 + cp;
            *(__half2*)(C + (size_t)row*NN + col) =
                __floats2half2_rn(acc[fm][fn][0], acc[fm][fn][1]);
            *(__half2*)(C + (size_t)(row+8)*NN + col) =
                __floats2half2_rn(acc[fm][fn][2], acc[fm][fn][3]);
        }
}

// ---------------- K3f: R12 version — 128-row, vectorized transpose-LN -------
__global__ __launch_bounds__(256, 3) void k3f(float* __restrict__ out,
                                              const float* __restrict__ cnw,
                                              const float* __restrict__ cnb,
                                              const float* __restrict__ ob)
{
    extern __shared__ char sb[];
    uint32_t sbase = smem_u32(sb);
    __half* tileH = (__half*)(sb + BHI);   // 128 x 136 halves = 34816 B
    float* psum  = (float*)(sb + PSUM);    // [4][128]
    float* psq   = (float*)(sb + PSQ);     // [4][128]
    int tid = threadIdx.x, wid = tid >> 5, lane = tid & 31;
    int r0 = blockIdx.x * 128;             // = i*512 + jbase

    // ---- load 128(c) x 128(j) fp16 tile of g_einH, coalesced ----
#pragma unroll
    for (int q = 0; q < 8; q++) {
        int idx = tid + q*256;             // uint4 index, 2048 total
        int c = idx >> 4, col8 = idx & 15;
        uint4 v = *(const uint4*)(g_einH + (size_t)c*NROW + r0 + col8*8);
        *(uint4*)((char*)tileH + c*272 + col8*16) = v;
    }
    __syncthreads();

    // ---- LN over c, vectorized: thread = (j-pair jp, c-quarter cq) ----
    {
        int jp = tid & 63, cq = tid >> 6;  // jp: 0..63, cq: 0..3
        int j0 = jp*2;
        float2 s = {0.f, 0.f}, q2 = {0.f, 0.f};
#pragma unroll 8
        for (int c2 = 0; c2 < 32; c2++) {
            int c = cq*32 + c2;
            float2 v = __half22float2(*(const __half2*)(tileH + c*TFSH + j0));
            s.x += v.x; s.y += v.y;
            q2.x += v.x*v.x; q2.y += v.y*v.y;
        }
        *(float2*)(psum + cq*128 + j0) = s;
        *(float2*)(psq  + cq*128 + j0) = q2;
        __syncthreads();
        float2 st = {0.f, 0.f}, sqt = {0.f, 0.f};
#pragma unroll
        for (int c4 = 0; c4 < 4; c4++) {
            float2 a = *(const float2*)(psum + c4*128 + j0);
            float2 b = *(const float2*)(psq  + c4*128 + j0);
            st.x += a.x; st.y += a.y; sqt.x += b.x; sqt.y += b.y;
        }
        float m0 = st.x * (1.f/CZ), m1 = st.y * (1.f/CZ);
        float rs0 = rsqrtf(sqt.x*(1.f/CZ) - m0*m0 + 1e-5f);
        float rs1 = rsqrtf(sqt.y*(1.f/CZ) - m1*m1 + 1e-5f);
#pragma unroll 8
        for (int c2 = 0; c2 < 32; c2++) {
            int c = cq*32 + ((c2 + jp) & 31);   // staggered banks
            float2 v = __half22float2(*(const __half2*)(tileH + c*TFSH + j0));
            float wc = __ldg(cnw + c), bc = __ldg(cnb + c);
            float y0 = (v.x - m0)*rs0*wc + bc;
            float y1 = (v.y - m1)*rs1*wc + bc;
            *(__half*)(sb + AHI + j0*ARS + c*2)     = __float2half_rn(y0);
            *(__half*)(sb + AHI + (j0+1)*ARS + c*2) = __float2half_rn(y1);
        }
    }
    __syncthreads();                       // A complete; tileH dead

    load_w_128(640, tid, sb, BHI);         // outp hi (overwrites tileH region)
    __syncthreads();

    int wm = wid & 3, wn = wid >> 2;
    int RM = wm*32, RNl = wn*32;
    int rr = lane >> 2, cp = (lane & 3)*2;

    uint32_t aOff[2], bOff[2], bOffP[2];
#pragma unroll
    for (int fm = 0; fm < 2; fm++)
        aOff[fm] = (uint32_t)((RM + fm*16 + (lane & 15))*ARS + (lane >> 4)*16);
#pragma unroll
    for (int fp = 0; fp < 2; fp++) {
        bOff[fp]  = (uint32_t)((RNl + fp*16 + ((lane >> 4) << 3) + (lane & 7))*BRS
                               + ((lane >> 3) & 1)*16);
        bOffP[fp] = bOff[fp] + 64*BRS;
    }

    float acc[2][4][4];
    for (int nt = 0; nt < 2; nt++) {
        mma_tile1(sbase + AHI, sbase + BHI, aOff, nt ? bOffP : bOff, acc);
#pragma unroll
        for (int fm = 0; fm < 2; fm++) {
            int rowA = RM + fm*16 + rr;
#pragma unroll
            for (int fn = 0; fn < 4; fn++) {
                int c0 = nt*64 + RNl + fn*8 + cp;
                float2 obv = *(const float2*)(ob + c0);
                float2 glA = __half22float2(*(const __half2*)(g_glsig + (size_t)(r0 + rowA)*CZ + c0));
                float2 glB = __half22float2(*(const __half2*)(g_glsig + (size_t)(r0 + rowA + 8)*CZ + c0));
                float2 vA = { (acc[fm][fn][0] + obv.x)*glA.x,
                              (acc[fm][fn][1] + obv.y)*glA.y };
                float2 vB = { (acc[fm][fn][2] + obv.x)*glB.x,
                              (acc[fm][fn][3] + obv.y)*glB.y };
                *(float2*)(out + (size_t)(r0 + rowA)*CZ + c0)     = vA;
                *(float2*)(out + (size_t)(r0 + rowA + 8)*CZ + c0) = vB;
            }
        }
    }
}

// ---------------- launch ----------------------------------------------------
extern "C" void kernel_launch(void* const* d_in, const int* in_sizes, int n_in,
                              void* d_out, int out_size)
{
    const float* act = (const float*)d_in[0];
    const float* mask= (const float*)d_in[1];
    const float* lnw = (const float*)d_in[2];
    const float* lnb = (const float*)d_in[3];
    const float* pw  = (const float*)d_in[4];
    const float* pb  = (const float*)d_in[5];
    const float* gw  = (const float*)d_in[6];
    const float* gb  = (const float*)d_in[7];
    const float* cnw = (const float*)d_in[8];
    const float* cnb = (const float*)d_in[9];
    const float* ow  = (const float*)d_in[10];
    const float* ob  = (const float*)d_in[11];
    const float* glw = (const float*)d_in[12];
    const float* glb = (const float*)d_in[13];
    float* out = (float*)d_out;

    cudaFuncSetAttribute(k1,  cudaFuncAttributeMaxDynamicSharedMemorySize, SMEM13);
    cudaFuncSetAttribute(k3f, cudaFuncAttributeMaxDynamicSharedMemorySize, SMEM_K3);
    cudaFuncSetAttribute(k2,  cudaFuncAttributeMaxDynamicSharedMemorySize, SMEM_K2);

    wsplit<<<384, 256>>>(pw, gw, glw, ow);
    k1<<<NROW/128, 256, SMEM13>>>(act, mask, lnw, lnb, pb, gb, glb);
    k2<<<dim3(16, CZ), 256, SMEM_K2>>>();
    k3f<<<NROW/128, 256, SMEM_K3>>>(out, cnw, cnb, ob);
}

// round 15
// speedup vs baseline: 1.0923x; 1.0923x over previous
#include <cuda_runtime.h>
#include <cuda_fp16.h>
#include <math.h>
#include <stdint.h>

#define NN 512
#define CZ 128
#define NROW (NN*NN)          // 262144 rows

// ---------------- scratch (static device globals) ---------------------------
__device__ __half g_LThi[(size_t)CZ*NROW];  // [c][i*512+k] fp16
__device__ __half g_RThi[(size_t)CZ*NROW];  // [c][j*512+k] fp16
__device__ __half g_glsig[(size_t)NROW*CZ]; // fp16, row-major (r, c)
__device__ __half g_einH [(size_t)CZ*NROW]; // [c][i*512+j] fp16
// weights fp16 (hi only), [n][k]: rows 0-255 gate, 256-511 proj, 512-639 gl, 640-767 outp
__device__ __half g_Whi[768*128];

// ======================= PTX helpers (sm_103-safe) ==========================
__device__ __forceinline__ uint32_t smem_u32(const void* p) {
    uint32_t a;
    asm("{ .reg .u64 t; cvta.to.shared.u64 t, %1; cvt.u32.u64 %0, t; }" : "=r"(a) : "l"(p));
    return a;
}
__device__ __forceinline__ void ldsm4(uint32_t r[4], uint32_t addr) {
    asm volatile("ldmatrix.sync.aligned.m8n8.x4.shared.b16 {%0,%1,%2,%3}, [%4];"
        : "=r"(r[0]), "=r"(r[1]), "=r"(r[2]), "=r"(r[3]) : "r"(addr));
}
__device__ __forceinline__ void mma16816(float c[4], const uint32_t a[4],
                                         uint32_t b0, uint32_t b1) {
    asm volatile("mma.sync.aligned.m16n8k16.row.col.f32.f16.f16.f32 "
        "{%0,%1,%2,%3}, {%4,%5,%6,%7}, {%8,%9}, {%0,%1,%2,%3};"
        : "+f"(c[0]), "+f"(c[1]), "+f"(c[2]), "+f"(c[3])
        : "r"(a[0]), "r"(a[1]), "r"(a[2]), "r"(a[3]), "r"(b0), "r"(b1));
}
__device__ __forceinline__ void cp16(uint32_t dst, const void* src) {
    asm volatile("cp.async.cg.shared.global [%0], [%1], 16;" :: "r"(dst), "l"(src));
}
#define CP_COMMIT() asm volatile("cp.async.commit_group;" ::: "memory")
// fast sigmoid: MUFU.EX2 path + fast division; rel err ~1e-6 << 6.6e-4 budget
__device__ __forceinline__ float sigf(float x) {
    return __fdividef(1.f, 1.f + __expf(-x));
}

// ---------------- K0: weights -> fp16 ---------------------------------------
__global__ void wsplit(const float* __restrict__ pw, const float* __restrict__ gw,
                       const float* __restrict__ glw, const float* __restrict__ ow)
{
    int idx = blockIdx.x*256 + threadIdx.x;   // 384*256 = 98304 = 768*128
    int row = idx >> 7;
    float v;
    if      (row < 256) v = gw [idx];
    else if (row < 512) v = pw [idx - 256*128];
    else if (row < 640) v = glw[idx - 512*128];
    else                v = ow [idx - 640*128];
    g_Whi[idx] = __float2half_rn(v);
}

// =================== mma-based LN+GEMM machinery (k1/k3) ====================
#define ARS    272                 // A row stride  (128 fp16 = 256B + pad)
#define BRS    272
#define AHI    0                   // A: 128*272 = 34816
#define BHI    34816               // B hi: 128 rows -> 34816
#define STK1   69632               // k1 staging, COLUMN-major: [col][row], 64 cols x 272B
#define SCS    272                 // staging col stride (128 rows x 2B + 16 pad)
#define SMEM13 87040               // k1: A + Bhi + staging; 2 blocks/SM
// k3f: A + tileH(=BHI region, also weights after) + partials
#define TFSH   136                 // half stride of einH tile (272 B rows)
#define PSUM   69632               // 4 x 128 floats = 2048 B
#define PSQ    71680               // 4 x 128 floats
#define SMEM_K3 73728              // 3 blocks/SM

// LN 128 rows of src -> fp16 A tile in smem (row-major [row][k])
__device__ __forceinline__ void ln_quant(const float* __restrict__ src,
                                         const float* __restrict__ w,
                                         const float* __restrict__ b,
                                         int r0, int tid, char* sb)
{
    int wid = tid >> 5, lane = tid & 31;
    float4 wv = *(const float4*)(w + lane*4);
    float4 bv = *(const float4*)(b + lane*4);
#pragma unroll
    for (int q = 0; q < 16; q++) {
        int row = wid*16 + q;
        float4 x = *(const float4*)(src + (size_t)(r0+row)*CZ + lane*4);
        float s  = x.x+x.y+x.z+x.w;
        float sq = x.x*x.x + x.y*x.y + x.z*x.z + x.w*x.w;
#pragma unroll
        for (int o = 16; o > 0; o >>= 1) {
            s  += __shfl_xor_sync(0xffffffffu, s,  o);
            sq += __shfl_xor_sync(0xffffffffu, sq, o);
        }
        float m  = s * (1.f/CZ);
        float v  = sq * (1.f/CZ) - m*m;
        float rs = rsqrtf(v + 1e-5f);
        float y0 = (x.x-m)*rs*wv.x + bv.x;
        float y1 = (x.y-m)*rs*wv.y + bv.y;
        float y2 = (x.z-m)*rs*wv.z + bv.z;
        float y3 = (x.w-m)*rs*wv.w + bv.w;
        uint32_t off = (uint32_t)(row*ARS + lane*8);
        *(__half2*)(sb + AHI + off)     = __floats2half2_rn(y0, y1);
        *(__half2*)(sb + AHI + off + 4) = __floats2half2_rn(y2, y3);
    }
}

// gate rows 0-63 | proj rows 64-127 -> BHI
__device__ __forceinline__ void load_w_gp(int nt, int tid, char* sb)
{
#pragma unroll
    for (int q = 0; q < 8; q++) {
        int idx = tid + q*256;
        int row = idx >> 4, ch = idx & 15;
        int gr = (row < 64) ? (nt*64 + row) : (256 + nt*64 + row - 64);
        *(uint4*)(sb + BHI + row*BRS + ch*16) = *(const uint4*)(g_Whi + (size_t)gr*128 + ch*8);
    }
}

// 128 contiguous weight rows (base row0) -> BHI (gl: 512, outp: 640)
__device__ __forceinline__ void load_w_128(int row0, int tid, char* sb)
{
#pragma unroll
    for (int q = 0; q < 8; q++) {
        int idx = tid + q*256;
        int row = idx >> 4, ch = idx & 15;
        *(uint4*)(sb + BHI + row*BRS + ch*16) = *(const uint4*)(g_Whi + (size_t)(row0 + row)*128 + ch*8);
    }
}

// M=128 x N=64 x K=128, single-pass (hi only); warp tile 32x32
__device__ __forceinline__ void mma_tile1(uint32_t sbase, const uint32_t aOff[2],
                                          const uint32_t bOff[2], float acc[2][4][4])
{
#pragma unroll
    for (int fm = 0; fm < 2; fm++)
#pragma unroll
        for (int fn = 0; fn < 4; fn++)
#pragma unroll
            for (int e = 0; e < 4; e++) acc[fm][fn][e] = 0.f;
#pragma unroll
    for (int kk = 0; kk < 8; kk++) {
        uint32_t ah[2][4], bh[2][4];
#pragma unroll
        for (int fm = 0; fm < 2; fm++)
            ldsm4(ah[fm], sbase + AHI + aOff[fm] + kk*32);
#pragma unroll
        for (int fp = 0; fp < 2; fp++)
            ldsm4(bh[fp], sbase + BHI + bOff[fp] + kk*32);
#pragma unroll
        for (int fm = 0; fm < 2; fm++)
#pragma unroll
            for (int fn = 0; fn < 4; fn++) {
                int fp = fn >> 1, s = (fn & 1)*2;
                mma16816(acc[fm][fn], ah[fm], bh[fp][s], bh[fp][s+1]);
            }
    }
}

// dual-N variant: both 64-col halves sharing A fragments
__device__ __forceinline__ void mma_gp(uint32_t sbase, const uint32_t aOff[2],
                                       const uint32_t bOff[2], const uint32_t bOffP[2],
                                       float accG[2][4][4], float accP[2][4][4])
{
#pragma unroll
    for (int fm = 0; fm < 2; fm++)
#pragma unroll
        for (int fn = 0; fn < 4; fn++)
#pragma unroll
            for (int e = 0; e < 4; e++) { accG[fm][fn][e] = 0.f; accP[fm][fn][e] = 0.f; }
#pragma unroll
    for (int kk = 0; kk < 8; kk++) {
        uint32_t ah[2][4], bg[2][4], bp[2][4];
#pragma unroll
        for (int fm = 0; fm < 2; fm++)
            ldsm4(ah[fm], sbase + AHI + aOff[fm] + kk*32);
#pragma unroll
        for (int fp = 0; fp < 2; fp++) {
            ldsm4(bg[fp], sbase + BHI + bOff[fp]  + kk*32);
            ldsm4(bp[fp], sbase + BHI + bOffP[fp] + kk*32);
        }
#pragma unroll
        for (int fm = 0; fm < 2; fm++)
#pragma unroll
            for (int fn = 0; fn < 4; fn++) {
                int fp = fn >> 1, s = (fn & 1)*2;
                mma16816(accG[fm][fn], ah[fm], bg[fp][s], bg[fp][s+1]);
                mma16816(accP[fm][fn], ah[fm], bp[fp][s], bp[fp][s+1]);
            }
    }
}

// ---------------- K1: LN + gate/proj/gl, single-pass, writes L/R fp16 -------
__global__ __launch_bounds__(256, 2) void k1(const float* __restrict__ act,
                                             const float* __restrict__ mask,
                                             const float* __restrict__ lnw,
                                             const float* __restrict__ lnb,
                                             const float* __restrict__ pb,
                                             const float* __restrict__ gb,
                                             const float* __restrict__ glb)
{
    extern __shared__ char sb[];
    uint32_t sbase = smem_u32(sb);
    int tid = threadIdx.x, wid = tid >> 5, lane = tid & 31;
    int r0 = blockIdx.x * 128;
    int wm = wid & 3, wn = wid >> 2;
    int RM = wm*32, RNl = wn*32;
    int rr = lane >> 2, cp = (lane & 3)*2;

    uint32_t aOff[2], bOff[2], bOffP[2];
#pragma unroll
    for (int fm = 0; fm < 2; fm++)
        aOff[fm] = (uint32_t)((RM + fm*16 + (lane & 15))*ARS + (lane >> 4)*16);
#pragma unroll
    for (int fp = 0; fp < 2; fp++) {
        bOff[fp]  = (uint32_t)((RNl + fp*16 + ((lane >> 4) << 3) + (lane & 7))*BRS
                               + ((lane >> 3) & 1)*16);
        bOffP[fp] = bOff[fp] + 64*BRS;
    }

    // hoisted loop-invariant mask values (one pair per fm)
    float mk[2][2];
#pragma unroll
    for (int fm = 0; fm < 2; fm++) {
        int rowA = RM + fm*16 + rr;
        mk[fm][0] = mask[r0 + rowA];
        mk[fm][1] = mask[r0 + rowA + 8];
    }

    ln_quant(act, lnw, lnb, r0, tid, sb);

    float accG[2][4][4], accP[2][4][4];

    // ---- 4 tiles of 64 cols: gate+proj in one dual-N mma pass ----
    for (int nt = 0; nt < 4; nt++) {
        load_w_gp(nt, tid, sb);                    // gate hi | proj hi
        __syncthreads();                           // B visible; prior staging reads done
        mma_gp(sbase, aOff, bOff, bOffP, accG, accP);
#pragma unroll
        for (int fm = 0; fm < 2; fm++) {
            int rowA = RM + fm*16 + rr;
            float mkA = mk[fm][0];
            float mkB = mk[fm][1];
#pragma unroll
            for (int fn = 0; fn < 4; fn++) {
                int cl = RNl + fn*8 + cp;
                float2 gbv = *(const float2*)(gb + nt*64 + cl);
                float2 pbv = *(const float2*)(pb + nt*64 + cl);
                float sA0 = sigf(accG[fm][fn][0] + gbv.x);
                float sA1 = sigf(accG[fm][fn][1] + gbv.y);
                float sB0 = sigf(accG[fm][fn][2] + gbv.x);
                float sB1 = sigf(accG[fm][fn][3] + gbv.y);
                float vA0 = mkA*(accP[fm][fn][0] + pbv.x)*sA0;
                float vA1 = mkA*(accP[fm][fn][1] + pbv.y)*sA1;
                float vB0 = mkB*(accP[fm][fn][2] + pbv.x)*sB0;
                float vB1 = mkB*(accP[fm][fn][3] + pbv.y)*sB1;
                // column-major staging: [col][row], scalar stores
                uint32_t o = (uint32_t)(STK1 + cl*SCS + rowA*2);
                *(__half*)(sb + o)             = __float2half_rn(vA0);   // (rowA,   cl)
                *(__half*)(sb + o + SCS)       = __float2half_rn(vA1);   // (rowA,   cl+1)
                *(__half*)(sb + o + 16)        = __float2half_rn(vB0);   // (rowA+8, cl)
                *(__half*)(sb + o + SCS + 16)  = __float2half_rn(vB1);   // (rowA+8, cl+1)
            }
        }
        __syncthreads();                           // staging visible
        {
            // read column cl rows rs..rs+31 as 4x uint4 (already in global order)
            __half* dst = (nt < 2) ? g_LThi : g_RThi;
            int cl = tid >> 2, rs = (tid & 3)*32;
            size_t go = (size_t)((nt & 1)*64 + cl)*NROW + r0 + rs;
            uint32_t so = (uint32_t)(STK1 + cl*SCS + rs*2);
#pragma unroll
            for (int s = 0; s < 4; s++)
                *(uint4*)(dst + go + s*8) = *(const uint4*)(sb + so + s*16);
        }
    }

    __syncthreads();                               // staging reads finished

    // ---- gl gate: dual-N single pass ----
    load_w_128(512, tid, sb);
    __syncthreads();
    mma_gp(sbase, aOff, bOff, bOffP, accG, accP);
#pragma unroll
    for (int fm = 0; fm < 2; fm++) {
        int rowA = RM + fm*16 + rr;
#pragma unroll
        for (int fn = 0; fn < 4; fn++) {
            int cl = RNl + fn*8 + cp;
            float2 b0 = *(const float2*)(glb + cl);
            float2 b1 = *(const float2*)(glb + 64 + cl);
            *(__half2*)(g_glsig + (size_t)(r0 + rowA)*CZ + cl) =
                __floats2half2_rn(sigf(accG[fm][fn][0] + b0.x), sigf(accG[fm][fn][1] + b0.y));
            *(__half2*)(g_glsig + (size_t)(r0 + rowA + 8)*CZ + cl) =
                __floats2half2_rn(sigf(accG[fm][fn][2] + b0.x), sigf(accG[fm][fn][3] + b0.y));
            *(__half2*)(g_glsig + (size_t)(r0 + rowA)*CZ + 64 + cl) =
                __floats2half2_rn(sigf(accP[fm][fn][0] + b1.x), sigf(accP[fm][fn][1] + b1.y));
            *(__half2*)(g_glsig + (size_t)(r0 + rowA + 8)*CZ + 64 + cl) =
                __floats2half2_rn(sigf(accP[fm][fn][2] + b1.x), sigf(accP[fm][fn][3] + b1.y));
        }
    }
}

// ---------------- K2: fp16 single-pass GEMM, K-chunk 64, 3-stage ------------
#define RSTRIDE 144
#define KCOMP   (128*RSTRIDE)       // 18432
#define ST_A    0
#define ST_BH   KCOMP
#define STAGE   (2*KCOMP)           // 36864
#define SMEM_K2 (3*STAGE)           // 110592 -> 2 blocks/SM

__device__ __forceinline__ void k2_compute(uint32_t sbk, const uint32_t aOff[2],
                                           const uint32_t bOff[4], float acc[2][8][4])
{
#pragma unroll
    for (int kk = 0; kk < 4; kk++) {
        uint32_t ah[2][4], bh[4][4];
#pragma unroll
        for (int fm = 0; fm < 2; fm++)
            ldsm4(ah[fm], sbk + ST_A + aOff[fm] + kk*32);
#pragma unroll
        for (int fp = 0; fp < 4; fp++)
            ldsm4(bh[fp], sbk + ST_BH + bOff[fp] + kk*32);
#pragma unroll
        for (int fm = 0; fm < 2; fm++)
#pragma unroll
            for (int fn = 0; fn < 8; fn++) {
                int fp = fn >> 1, s = (fn & 1)*2;
                mma16816(acc[fm][fn], ah[fm], bh[fp][s], bh[fp][s+1]);
            }
    }
}

__device__ __forceinline__ void k2_copy(uint32_t st, const __half* Ah,
                                        const __half* Bh, int k0, int tid)
{
#pragma unroll
    for (int q = 0; q < 4; q++) {
        int idx = tid + q*256;          // 0..1023
        int r = idx >> 3, kg = idx & 7;
        size_t go = (size_t)r*NN + k0 + kg*8;
        uint32_t so = (uint32_t)(r*RSTRIDE + kg*16);
        cp16(st + ST_A  + so, Ah + go);
        cp16(st + ST_BH + so, Bh + go);
    }
}

__global__ __launch_bounds__(256, 2) void k2()
{
    extern __shared__ char sb[];
    uint32_t sbase = smem_u32(sb);
    int tid = threadIdx.x, wid = tid >> 5, lane = tid & 31;
    int c  = blockIdx.y;
    int ti = blockIdx.x >> 2, tj = blockIdx.x & 3;

    const __half* Ah = g_LThi + (size_t)c*NROW + (size_t)ti*128*NN;
    const __half* Bh = g_RThi + (size_t)c*NROW + (size_t)tj*128*NN;
    __half* C = g_einH + (size_t)c*NROW + (size_t)(ti*128)*NN + tj*128;

    int wm = wid & 3, wn = wid >> 2;
    int RM = wm*32, RN = wn*64;

    uint32_t aOff[2], bOff[4];
#pragma unroll
    for (int fm = 0; fm < 2; fm++)
        aOff[fm] = (uint32_t)((RM + fm*16 + (lane & 15))*RSTRIDE + (lane >> 4)*16);
#pragma unroll
    for (int fp = 0; fp < 4; fp++)
        bOff[fp] = (uint32_t)((RN + fp*16 + ((lane >> 4) << 3) + (lane & 7))*RSTRIDE
                              + ((lane >> 3) & 1)*16);

    float acc[2][8][4];
#pragma unroll
    for (int fm = 0; fm < 2; fm++)
#pragma unroll
        for (int fn = 0; fn < 8; fn++)
#pragma unroll
            for (int e = 0; e < 4; e++) acc[fm][fn][e] = 0.f;

    k2_copy(sbase + 0*STAGE, Ah, Bh, 0,  tid); CP_COMMIT();
    k2_copy(sbase + 1*STAGE, Ah, Bh, 64, tid); CP_COMMIT();

    for (int t = 0; t < 8; t++) {
        if (t < 7) asm volatile("cp.async.wait_group 1;" ::: "memory");
        else       asm volatile("cp.async.wait_group 0;" ::: "memory");
        __syncthreads();
        if (t + 2 < 8) {
            k2_copy(sbase + ((t+2)%3)*STAGE, Ah, Bh, (t+2)*64, tid);
            CP_COMMIT();
        }
        k2_compute(sbase + (t%3)*STAGE, aOff, bOff, acc);
    }

    int rr = lane >> 2, cp = (lane & 3)*2;
#pragma unroll
    for (int fm = 0; fm < 2; fm++)
#pragma unroll
        for (int fn = 0; fn < 8; fn++) {
            int row = RM + fm*16 + rr;
            int col = RN + fn*8 + cp;
            *(__half2*)(C + (size_t)row*NN + col) =
                __floats2half2_rn(acc[fm][fn][0], acc[fm][fn][1]);
            *(__half2*)(C + (size_t)(row+8)*NN + col) =
                __floats2half2_rn(acc[fm][fn][2], acc[fm][fn][3]);
        }
}

// ---------------- K3f: einH tile + vectorized transpose-LN + outp + gl ------
__global__ __launch_bounds__(256, 3) void k3f(float* __restrict__ out,
                                              const float* __restrict__ cnw,
                                              const float* __restrict__ cnb,
                                              const float* __restrict__ ob)
{
    extern __shared__ char sb[];
    uint32_t sbase = smem_u32(sb);
    __half* tileH = (__half*)(sb + BHI);   // 128 x 136 halves = 34816 B
    float* psum  = (float*)(sb + PSUM);    // [4][128]
    float* psq   = (float*)(sb + PSQ);     // [4][128]
    int tid = threadIdx.x, wid = tid >> 5, lane = tid & 31;
    int r0 = blockIdx.x * 128;             // = i*512 + jbase

    // ---- load 128(c) x 128(j) fp16 tile of g_einH, coalesced ----
#pragma unroll
    for (int q = 0; q < 8; q++) {
        int idx = tid + q*256;             // uint4 index, 2048 total
        int c = idx >> 4, col8 = idx & 15;
        uint4 v = *(const uint4*)(g_einH + (size_t)c*NROW + r0 + col8*8);
        *(uint4*)((char*)tileH + c*272 + col8*16) = v;
    }
    __syncthreads();

    // ---- LN over c, vectorized: thread = (j-pair jp, c-quarter cq) ----
    {
        int jp = tid & 63, cq = tid >> 6;  // jp: 0..63, cq: 0..3
        int j0 = jp*2;
        float2 s = {0.f, 0.f}, q2 = {0.f, 0.f};
#pragma unroll 8
        for (int c2 = 0; c2 < 32; c2++) {
            int c = cq*32 + c2;
            float2 v = __half22float2(*(const __half2*)(tileH + c*TFSH + j0));
            s.x += v.x; s.y += v.y;
            q2.x += v.x*v.x; q2.y += v.y*v.y;
        }
        *(float2*)(psum + cq*128 + j0) = s;
        *(float2*)(psq  + cq*128 + j0) = q2;
        __syncthreads();
        float2 st = {0.f, 0.f}, sqt = {0.f, 0.f};
#pragma unroll
        for (int c4 = 0; c4 < 4; c4++) {
            float2 a = *(const float2*)(psum + c4*128 + j0);
            float2 b = *(const float2*)(psq  + c4*128 + j0);
            st.x += a.x; st.y += a.y; sqt.x += b.x; sqt.y += b.y;
        }
        float m0 = st.x * (1.f/CZ), m1 = st.y * (1.f/CZ);
        float rs0 = rsqrtf(sqt.x*(1.f/CZ) - m0*m0 + 1e-5f);
        float rs1 = rsqrtf(sqt.y*(1.f/CZ) - m1*m1 + 1e-5f);
        // normalize this thread's c-quarter for both j's; c staggered by jp
        // so the scalar A stores hit distinct banks.
#pragma unroll 8
        for (int c2 = 0; c2 < 32; c2++) {
            int c = cq*32 + ((c2 + jp) & 31);
            float2 v = __half22float2(*(const __half2*)(tileH + c*TFSH + j0));
            float wc = __ldg(cnw + c), bc = __ldg(cnb + c);
            float y0 = (v.x - m0)*rs0*wc + bc;
            float y1 = (v.y - m1)*rs1*wc + bc;
            *(__half*)(sb + AHI + j0*ARS + c*2)       = __float2half_rn(y0);
            *(__half*)(sb + AHI + (j0+1)*ARS + c*2)   = __float2half_rn(y1);
        }
    }
    __syncthreads();                       // A complete; tileH dead

    load_w_128(640, tid, sb);              // outp hi (overwrites tileH region)
    __syncthreads();

    int wm = wid & 3, wn = wid >> 2;
    int RM = wm*32, RNl = wn*32;
    int rr = lane >> 2, cp = (lane & 3)*2;

    uint32_t aOff[2], bOff[2], bOffP[2];
#pragma unroll
    for (int fm = 0; fm < 2; fm++)
        aOff[fm] = (uint32_t)((RM + fm*16 + (lane & 15))*ARS + (lane >> 4)*16);
#pragma unroll
    for (int fp = 0; fp < 2; fp++) {
        bOff[fp]  = (uint32_t)((RNl + fp*16 + ((lane >> 4) << 3) + (lane & 7))*BRS
                               + ((lane >> 3) & 1)*16);
        bOffP[fp] = bOff[fp] + 64*BRS;
    }

    float acc[2][4][4];
    for (int nt = 0; nt < 2; nt++) {
        mma_tile1(sbase, aOff, nt ? bOffP : bOff, acc);
#pragma unroll
        for (int fm = 0; fm < 2; fm++) {
            int rowA = RM + fm*16 + rr;
#pragma unroll
            for (int fn = 0; fn < 4; fn++) {
                int c0 = nt*64 + RNl + fn*8 + cp;
                float2 obv = *(const float2*)(ob + c0);
                float2 glA = __half22float2(*(const __half2*)(g_glsig + (size_t)(r0 + rowA)*CZ + c0));
                float2 glB = __half22float2(*(const __half2*)(g_glsig + (size_t)(r0 + rowA + 8)*CZ + c0));
                float2 vA = { (acc[fm][fn][0] + obv.x)*glA.x,
                              (acc[fm][fn][1] + obv.y)*glA.y };
                float2 vB = { (acc[fm][fn][2] + obv.x)*glB.x,
                              (acc[fm][fn][3] + obv.y)*glB.y };
                *(float2*)(out + (size_t)(r0 + rowA)*CZ + c0)     = vA;
                *(float2*)(out + (size_t)(r0 + rowA + 8)*CZ + c0) = vB;
            }
        }
    }
}

// ---------------- launch ----------------------------------------------------
extern "C" void kernel_launch(void* const* d_in, const int* in_sizes, int n_in,
                              void* d_out, int out_size)
{
    const float* act = (const float*)d_in[0];
    const float* mask= (const float*)d_in[1];
    const float* lnw = (const float*)d_in[2];
    const float* lnb = (const float*)d_in[3];
    const float* pw  = (const float*)d_in[4];
    const float* pb  = (const float*)d_in[5];
    const float* gw  = (const float*)d_in[6];
    const float* gb  = (const float*)d_in[7];
    const float* cnw = (const float*)d_in[8];
    const float* cnb = (const float*)d_in[9];
    const float* ow  = (const float*)d_in[10];
    const float* ob  = (const float*)d_in[11];
    const float* glw = (const float*)d_in[12];
    const float* glb = (const float*)d_in[13];
    float* out = (float*)d_out;

    cudaFuncSetAttribute(k1,  cudaFuncAttributeMaxDynamicSharedMemorySize, SMEM13);
    cudaFuncSetAttribute(k3f, cudaFuncAttributeMaxDynamicSharedMemorySize, SMEM_K3);
    cudaFuncSetAttribute(k2,  cudaFuncAttributeMaxDynamicSharedMemorySize, SMEM_K2);

    wsplit<<<384, 256>>>(pw, gw, glw, ow);
    k1<<<NROW/128, 256, SMEM13>>>(act, mask, lnw, lnb, pb, gb, glb);
    k2<<<dim3(16, CZ), 256, SMEM_K2>>>();
    k3f<<<NROW/128, 256, SMEM_K3>>>(out, cnw, cnb, ob);
}